// round 7
// baseline (speedup 1.0000x reference)
#include <cuda_runtime.h>
#include <cuda_bf16.h>
#include <cstdint>
#include <math.h>

#define NT 16384
#define HH 2048
#define NE 64
#define NB 4
#define NS 4096
#define TM 128          // tokens per CTA
#define THREADS 256
// FFMA path: K [0, 1280), tiles of 32
#define NTF 40
// HMMA path: K [1280, 2048), tiles of 64
#define NTH 12
#define KOFF_H 1280
#define SMEM_BYTES 147712
#define TAU 1e-4f
#define MAXFIX 4096

// persistent scratch (allocation-free rule: __device__ globals)
__device__ float    g_ssum[NB * NE];
__device__ int      g_cnt[NB * NE];
__device__ uint32_t g_w0[NE * HH / 2];   // bf16x2-packed W plane 0 (hi)
__device__ uint32_t g_w1[NE * HH / 2];   // plane 1 (residual)
__device__ int      g_nfix;
__device__ int      g_fix[MAXFIX];

// ---------------- helpers ----------------
__device__ __forceinline__ uint32_t smem_u32(const void* p) {
    uint32_t a;
    asm("{ .reg .u64 t; cvta.to.shared.u64 t, %1; cvt.u32.u64 %0, t; }" : "=r"(a) : "l"(p));
    return a;
}
__device__ __forceinline__ uint32_t pack2(float lo, float hi) {
    uint32_t r;
    asm("cvt.rn.bf16x2.f32 %0, %1, %2;" : "=r"(r) : "f"(hi), "f"(lo));
    return r;
}
__device__ __forceinline__ void ldsm4(uint32_t* r, uint32_t addr) {
    asm volatile("ldmatrix.sync.aligned.m8n8.x4.shared.b16 {%0,%1,%2,%3}, [%4];"
                 : "=r"(r[0]), "=r"(r[1]), "=r"(r[2]), "=r"(r[3]) : "r"(addr));
}
__device__ __forceinline__ void mma16816(float* d, const uint32_t* a, const uint32_t* b) {
    asm volatile("mma.sync.aligned.m16n8k16.row.col.f32.bf16.bf16.f32 "
                 "{%0,%1,%2,%3}, {%4,%5,%6,%7}, {%8,%9}, {%0,%1,%2,%3};"
                 : "+f"(d[0]), "+f"(d[1]), "+f"(d[2]), "+f"(d[3])
                 : "r"(a[0]), "r"(a[1]), "r"(a[2]), "r"(a[3]), "r"(b[0]), "r"(b[1]));
}
__device__ __forceinline__ void split2(float u, float v, uint32_t& p0, uint32_t& p1) {
    p0 = pack2(u, v);
    float u0 = __uint_as_float(p0 << 16);
    float v0 = __uint_as_float(p0 & 0xffff0000u);
    p1 = pack2(u - u0, v - v0);
}
#define FMA2(acc, a2, b2) \
    asm("fma.rn.f32x2 %0, %1, %2, %0;" : "+l"(acc) : "l"(a2), "l"(b2))
#define DUP2(d, s) \
    asm("mov.b64 %0, {%1, %1};" : "=l"(d) : "r"(s))

// ---------------- W split kernel (+ fixup counter reset) ----------------
__global__ __launch_bounds__(256) void k_wconv(const float* __restrict__ W) {
    if (blockIdx.x == 0 && threadIdx.x == 0) g_nfix = 0;
    int i = (blockIdx.x * 256 + threadIdx.x) * 4;
    float4 v = *(const float4*)(W + i);
    uint32_t a0, a1, b0, b1;
    split2(v.x, v.y, a0, a1);
    split2(v.z, v.w, b0, b1);
    ((uint2*)g_w0)[i >> 2] = make_uint2(a0, b0);
    ((uint2*)g_w1)[i >> 2] = make_uint2(a1, b1);
}

// ---------------- main gate kernel: FFMA(fp32) + HMMA(bf16x2) hybrid ----------------
__global__ __launch_bounds__(THREADS, 1)
void k_gate(const float* __restrict__ X, const float* __restrict__ W,
            float* __restrict__ out, int wbase) {
    extern __shared__ char smem[];
    const int tid  = threadIdx.x;
    const int wid  = tid >> 5;
    const int lane = tid & 31;
    const uint32_t sb = smem_u32(smem);
    const int tokBase = blockIdx.x * TM;

    int* scnt = (int*)(smem + 147456);
    if (tid < NE) scnt[tid] = 0;

    // ---- smem map ----
    // FFMA: xs[s][k][tok] @ sb + s*16384 (row 512B); ws[s][k][e] @ sb+32768+s*8192 (row 256B)
    // HMMA: HA0[s]@49152+s*16384, HA1[s]@81920+s*16384, HB0[s]@114688+s*8192, HB1[s]@131072+s*8192
    const uint32_t FXS = sb, FWS = sb + 32768u;
    const uint32_t HA0 = sb + 49152u, HA1 = sb + 81920u;
    const uint32_t HB0 = sb + 114688u, HB1 = sb + 131072u;

    // ======== FFMA addressing (round-5 layout) ========
    const int xtok  = tid >> 1;
    const int xqsel = tid & 1;
    const float* fxp = X + (size_t)(tokBase + xtok) * HH + xqsel * 16;
    const int fwe  = tid & 63;
    const int fwq2 = tid >> 6;
    const float* fwp = W + (size_t)fwe * HH + fwq2 * 4;
    const uint32_t aOff = (uint32_t)lane * 16u;
    const uint32_t bOff = (uint32_t)wid * 32u;

    // ======== HMMA addressing (round-4 layout) ========
    const int hxr = tid >> 4;
    const float* hxp = X + (size_t)(tokBase + hxr) * HH + KOFF_H + (tid & 15) * 4;
    const int hwr = tid >> 3;
    const int hwc = tid & 7;
    const int hwbase4 = hwr * 256 + hwc;        // uint4 idx into W-plane row
    uint32_t hxoff[8], hwoff[2];
#pragma unroll
    for (int p = 0; p < 8; p++) {
        uint32_t off = (uint32_t)(hxr + 16 * p) * 128u + (uint32_t)(tid & 15) * 8u;
        hxoff[p] = off ^ ((off >> 3) & 0x70);
    }
#pragma unroll
    for (int q = 0; q < 2; q++) {
        uint32_t off = (uint32_t)(hwr + 32 * q) * 128u + (uint32_t)hwc * 16u;
        hwoff[q] = off ^ ((off >> 3) & 0x70);
    }
    const int wm = wid & 3;
    const int wn = wid >> 2;
    const uint32_t xorK  = (uint32_t)(lane & 7);
    const uint32_t kselA = (uint32_t)(lane >> 4);
    const uint32_t kselB = (uint32_t)((lane >> 3) & 1);
    uint32_t rowA[2], rowB[2];
#pragma unroll
    for (int mt = 0; mt < 2; mt++)
        rowA[mt] = (uint32_t)(wm * 32 + mt * 16 + (lane & 15)) * 128u;
    {
        int nB = ((lane >> 4) * 8) + (lane & 7);
#pragma unroll
        for (int pr = 0; pr < 2; pr++)
            rowB[pr] = (uint32_t)(wn * 32 + pr * 16 + nB) * 128u;
    }

    // accumulators
    unsigned long long facc[4][4];
#pragma unroll
    for (int i = 0; i < 4; i++)
#pragma unroll
        for (int e = 0; e < 4; e++) facc[i][e] = 0ull;
    float hacc[2][4][4];
#pragma unroll
    for (int mt = 0; mt < 2; mt++)
#pragma unroll
        for (int q = 0; q < 4; q++)
#pragma unroll
            for (int e = 0; e < 4; e++) hacc[mt][q][e] = 0.0f;

    // ======== prologue ========
    float4 fxv[4]; float4 fwv[2];
#pragma unroll
    for (int p = 0; p < 4; p++) fxv[p] = *(const float4*)(fxp + p * 4);
#pragma unroll
    for (int p = 0; p < 2; p++) fwv[p] = *(const float4*)(fwp + p * 16);

    float4 hx[8]; uint4 hw0[2], hw1[2];
#pragma unroll
    for (int p = 0; p < 8; p++) hx[p] = *(const float4*)(hxp + (size_t)p * 16 * HH);
#pragma unroll
    for (int q = 0; q < 2; q++) {
        hw0[q] = ((const uint4*)g_w0)[hwbase4 + 160 + q * 8192];
        hw1[q] = ((const uint4*)g_w1)[hwbase4 + 160 + q * 8192];
    }
    // STS HMMA tile 0 -> buf 0
    {
#pragma unroll
        for (int p = 0; p < 8; p++) {
            uint32_t p0a, p1a, p0b, p1b;
            split2(hx[p].x, hx[p].y, p0a, p1a);
            split2(hx[p].z, hx[p].w, p0b, p1b);
            asm volatile("st.shared.v2.u32 [%0], {%1,%2};" :: "r"(HA0 + hxoff[p]), "r"(p0a), "r"(p0b));
            asm volatile("st.shared.v2.u32 [%0], {%1,%2};" :: "r"(HA1 + hxoff[p]), "r"(p1a), "r"(p1b));
        }
#pragma unroll
        for (int q = 0; q < 2; q++) {
            asm volatile("st.shared.v4.b32 [%0], {%1,%2,%3,%4};"
                         :: "r"(HB0 + hwoff[q]), "r"(hw0[q].x), "r"(hw0[q].y), "r"(hw0[q].z), "r"(hw0[q].w));
            asm volatile("st.shared.v4.b32 [%0], {%1,%2,%3,%4};"
                         :: "r"(HB1 + hwoff[q]), "r"(hw1[q].x), "r"(hw1[q].y), "r"(hw1[q].z), "r"(hw1[q].w));
        }
    }

    // ======== main loop ========
    for (int i = 0; i < NTF; i++) {
        const int j  = i / 3;          // hmma tile group
        const int ph = i - 3 * j;      // phase 0/1/2
        const int sF = i & 1;
        const uint32_t fxsb = FXS + (uint32_t)sF * 16384u;
        const uint32_t fwsb = FWS + (uint32_t)sF * 8192u;

        // ---- STS FFMA tile i (from regs) ----
#pragma unroll
        for (int p = 0; p < 4; p++) {
            const uint32_t kq = (uint32_t)(xqsel * 4 + p);
            const uint32_t a0 = fxsb + kq * 4u * 512u + (uint32_t)xtok * 4u;
            asm volatile("st.shared.f32 [%0], %1;" :: "r"(a0),         "f"(fxv[p].x));
            asm volatile("st.shared.f32 [%0], %1;" :: "r"(a0 + 512u),  "f"(fxv[p].y));
            asm volatile("st.shared.f32 [%0], %1;" :: "r"(a0 + 1024u), "f"(fxv[p].z));
            asm volatile("st.shared.f32 [%0], %1;" :: "r"(a0 + 1536u), "f"(fxv[p].w));
        }
#pragma unroll
        for (int p = 0; p < 2; p++) {
            const uint32_t kq = (uint32_t)(fwq2 + 4 * p);
            const uint32_t a0 = fwsb + kq * 4u * 256u + (uint32_t)fwe * 4u;
            asm volatile("st.shared.f32 [%0], %1;" :: "r"(a0),         "f"(fwv[p].x));
            asm volatile("st.shared.f32 [%0], %1;" :: "r"(a0 + 256u),  "f"(fwv[p].y));
            asm volatile("st.shared.f32 [%0], %1;" :: "r"(a0 + 512u),  "f"(fwv[p].z));
            asm volatile("st.shared.f32 [%0], %1;" :: "r"(a0 + 768u),  "f"(fwv[p].w));
        }

        // ---- phase 2: convert + STS HMMA tile j+1 -> buf (j+1)&1 ----
        if (ph == 2 && j + 1 < NTH) {
            const uint32_t sH = (uint32_t)((j + 1) & 1) * 16384u;
            const uint32_t sHb = (uint32_t)((j + 1) & 1) * 8192u;
#pragma unroll
            for (int p = 0; p < 8; p++) {
                uint32_t p0a, p1a, p0b, p1b;
                split2(hx[p].x, hx[p].y, p0a, p1a);
                split2(hx[p].z, hx[p].w, p0b, p1b);
                asm volatile("st.shared.v2.u32 [%0], {%1,%2};" :: "r"(HA0 + sH + hxoff[p]), "r"(p0a), "r"(p0b));
                asm volatile("st.shared.v2.u32 [%0], {%1,%2};" :: "r"(HA1 + sH + hxoff[p]), "r"(p1a), "r"(p1b));
            }
#pragma unroll
            for (int q = 0; q < 2; q++) {
                asm volatile("st.shared.v4.b32 [%0], {%1,%2,%3,%4};"
                             :: "r"(HB0 + sHb + hwoff[q]), "r"(hw0[q].x), "r"(hw0[q].y), "r"(hw0[q].z), "r"(hw0[q].w));
                asm volatile("st.shared.v4.b32 [%0], {%1,%2,%3,%4};"
                             :: "r"(HB1 + sHb + hwoff[q]), "r"(hw1[q].x), "r"(hw1[q].y), "r"(hw1[q].z), "r"(hw1[q].w));
            }
        }

        __syncthreads();

        // ---- HMMA chunk: ks per phase (2,1,1) on tile j, buf j&1 ----
        if (j < NTH) {
            const uint32_t sH  = (uint32_t)(j & 1) * 16384u;
            const uint32_t sHb = (uint32_t)(j & 1) * 8192u;
            const int ks0 = (ph == 0) ? 0 : (ph + 1);   // 0(+1), 2, 3
            const int nks = (ph == 0) ? 2 : 1;
#pragma unroll
            for (int kk = 0; kk < 2; kk++) {
                if (kk >= nks) break;
                const int ks = ks0 + kk;
                const uint32_t kA = (uint32_t)(2 * ks) + kselA;
                const uint32_t kB = (uint32_t)(2 * ks) + kselB;
                uint32_t bf0[8], bf1[8];
#pragma unroll
                for (int pr = 0; pr < 2; pr++) {
                    ldsm4(&bf0[pr * 4], HB0 + sHb + rowB[pr] + ((kB ^ xorK) << 4));
                    ldsm4(&bf1[pr * 4], HB1 + sHb + rowB[pr] + ((kB ^ xorK) << 4));
                }
                uint32_t af0[2][4], af1[2][4];
                ldsm4(af0[0], HA0 + sH + rowA[0] + ((kA ^ xorK) << 4));
                ldsm4(af0[1], HA0 + sH + rowA[1] + ((kA ^ xorK) << 4));
                ldsm4(af1[0], HA1 + sH + rowA[0] + ((kA ^ xorK) << 4));
                ldsm4(af1[1], HA1 + sH + rowA[1] + ((kA ^ xorK) << 4));
#pragma unroll
                for (int mt = 0; mt < 2; mt++)
#pragma unroll
                    for (int q = 0; q < 4; q++) {
                        mma16816(hacc[mt][q], af0[mt], &bf0[q * 2]);
                        mma16816(hacc[mt][q], af0[mt], &bf1[q * 2]);
                        mma16816(hacc[mt][q], af1[mt], &bf0[q * 2]);
                    }
            }
        }

        // ---- prefetch FFMA tile i+1 ----
        if (i + 1 < NTF) {
            const int k0 = (i + 1) * 32;
#pragma unroll
            for (int p = 0; p < 4; p++) fxv[p] = *(const float4*)(fxp + k0 + p * 4);
#pragma unroll
            for (int p = 0; p < 2; p++) fwv[p] = *(const float4*)(fwp + k0 + p * 16);
        }
        // ---- phase 1: prefetch HMMA tile j+1 ----
        if (ph == 1 && j + 1 < NTH) {
            const int kj = (j + 1) * 64;
#pragma unroll
            for (int p = 0; p < 8; p++) hx[p] = *(const float4*)(hxp + kj + (size_t)p * 16 * HH);
#pragma unroll
            for (int q = 0; q < 2; q++) {
                hw0[q] = ((const uint4*)g_w0)[hwbase4 + 160 + (j + 1) * 8 + q * 8192];
                hw1[q] = ((const uint4*)g_w1)[hwbase4 + 160 + (j + 1) * 8 + q * 8192];
            }
        }

        // ---- FFMA2 over tile i ----
        const uint32_t aB = fxsb + aOff;
        const uint32_t bB = fwsb + bOff;
#pragma unroll
        for (int k = 0; k < 32; k++) {
            float a0, a1, a2, a3;
            asm("ld.shared.v4.f32 {%0,%1,%2,%3}, [%4];"
                : "=f"(a0), "=f"(a1), "=f"(a2), "=f"(a3)
                : "r"(aB + (uint32_t)k * 512u));
            unsigned long long b01, b23, b45, b67;
            asm("ld.shared.v2.u64 {%0,%1}, [%2];"
                : "=l"(b01), "=l"(b23) : "r"(bB + (uint32_t)k * 256u));
            asm("ld.shared.v2.u64 {%0,%1}, [%2];"
                : "=l"(b45), "=l"(b67) : "r"(bB + (uint32_t)k * 256u + 16u));

            unsigned long long ad0, ad1, ad2, ad3;
            DUP2(ad0, __float_as_uint(a0));
            DUP2(ad1, __float_as_uint(a1));
            DUP2(ad2, __float_as_uint(a2));
            DUP2(ad3, __float_as_uint(a3));

            FMA2(facc[0][0], ad0, b01); FMA2(facc[0][1], ad0, b23);
            FMA2(facc[0][2], ad0, b45); FMA2(facc[0][3], ad0, b67);
            FMA2(facc[1][0], ad1, b01); FMA2(facc[1][1], ad1, b23);
            FMA2(facc[1][2], ad1, b45); FMA2(facc[1][3], ad1, b67);
            FMA2(facc[2][0], ad2, b01); FMA2(facc[2][1], ad2, b23);
            FMA2(facc[2][2], ad2, b45); FMA2(facc[2][3], ad2, b67);
            FMA2(facc[3][0], ad3, b01); FMA2(facc[3][1], ad3, b23);
            FMA2(facc[3][2], ad3, b45); FMA2(facc[3][3], ad3, b67);
        }
    }

    __syncthreads();   // all buffers free; reuse as logits

    // ---- FFMA accumulators -> logits smem [128][66] ----
    float* Lg = (float*)smem;
#pragma unroll
    for (int i = 0; i < 4; i++) {
        const int tok = lane * 4 + i;
#pragma unroll
        for (int ep = 0; ep < 4; ep++) {
            uint32_t lo, hi;
            asm("mov.b64 {%0,%1}, %2;" : "=r"(lo), "=r"(hi) : "l"(facc[i][ep]));
            asm volatile("st.shared.v2.f32 [%0], {%1,%2};"
                         :: "r"(sb + (uint32_t)(tok * 66 + wid * 8 + ep * 2) * 4u),
                            "f"(__uint_as_float(lo)), "f"(__uint_as_float(hi)));
        }
    }
    __syncthreads();

    // ---- HMMA accumulators: add into logits ----
    {
        const int g  = lane >> 2;
        const int tg = lane & 3;
#pragma unroll
        for (int mt = 0; mt < 2; mt++)
#pragma unroll
            for (int q = 0; q < 4; q++) {
                int m0 = wm * 32 + mt * 16 + g;
                int c  = wn * 32 + q * 8 + tg * 2;
                Lg[m0 * 66 + c]           += hacc[mt][q][0];
                Lg[m0 * 66 + c + 1]       += hacc[mt][q][1];
                Lg[(m0 + 8) * 66 + c]     += hacc[mt][q][2];
                Lg[(m0 + 8) * 66 + c + 1] += hacc[mt][q][3];
            }
    }
    __syncthreads();

    // ---- per-token softmax / top-2 (+ near-tie flagging) ----
    if (tid < TM) {
        float v[64];
#pragma unroll
        for (int e = 0; e < NE; e++) v[e] = Lg[tid * 66 + e];

        float m = -1e30f;
#pragma unroll
        for (int e = 0; e < NE; e++) m = fmaxf(m, v[e]);

        float Z = 0.0f, b1 = -1e30f, b2 = -1e30f, b3 = -1e30f;
        int i1 = 0, i2 = 0;
#pragma unroll
        for (int e = 0; e < NE; e++) {
            float x = v[e];
            float ex = __expf(x - m);
            v[e] = ex;
            Z += ex;
            if (x > b1)      { b3 = b2; b2 = b1; i2 = i1; b1 = x; i1 = e; }
            else if (x > b2) { b3 = b2; b2 = x;  i2 = e; }
            else if (x > b3) { b3 = x; }
        }
        float invZ = 1.0f / Z;
        float s1 = v[i1] * invZ;
        float s2 = v[i2] * invZ;
        float den = s1 + s2 + 1e-20f;

        int gt = tokBase + tid;
        out[gt * 2 + 0] = (float)i1;
        out[gt * 2 + 1] = (float)i2;
        out[wbase + gt * 2 + 0] = s1 / den;
        out[wbase + gt * 2 + 1] = s2 / den;

        if ((b1 - b2 < TAU) || (b2 - b3 < TAU)) {
            int slot = atomicAdd(&g_nfix, 1);
            if (slot < MAXFIX) g_fix[slot] = gt;
        }

        atomicAdd(&scnt[i1], 1);
        atomicAdd(&scnt[i2], 1);

#pragma unroll
        for (int e = 0; e < NE; e++) Lg[tid * 66 + e] = v[e] * invZ;
    }
    __syncthreads();

    if (tid < NE) {
        float ssum = 0.0f;
        for (int r = 0; r < TM; r++) ssum += Lg[r * 66 + tid];
        const int b = tokBase >> 12;
        atomicAdd(&g_ssum[b * NE + tid], ssum);
        int c = scnt[tid];
        if (c) atomicAdd(&g_cnt[b * NE + tid], c);
    }
}

// ---------------- fp64 fixup for near-tie tokens ----------------
__global__ __launch_bounds__(256) void k_fixup(const float* __restrict__ X,
                                               const float* __restrict__ W,
                                               float* __restrict__ out, int wbase) {
    __shared__ double part[256];
    __shared__ double lg[64];
    int n = g_nfix;
    if (n > MAXFIX) n = MAXFIX;
    const int tid = threadIdx.x;
    const int e = tid & 63;
    const int j = tid >> 6;

    for (int s = blockIdx.x; s < n; s += gridDim.x) {
        int gt = g_fix[s];
        const float* xr = X + (size_t)gt * HH;
        const float* wr = W + (size_t)e * HH;
        double a0 = 0.0, a1 = 0.0, a2 = 0.0, a3 = 0.0;
        int k0 = j * 512;
#pragma unroll 4
        for (int k = k0; k < k0 + 512; k += 4) {
            a0 += (double)xr[k + 0] * (double)wr[k + 0];
            a1 += (double)xr[k + 1] * (double)wr[k + 1];
            a2 += (double)xr[k + 2] * (double)wr[k + 2];
            a3 += (double)xr[k + 3] * (double)wr[k + 3];
        }
        part[tid] = (a0 + a1) + (a2 + a3);
        __syncthreads();
        if (tid < 64) lg[e] = part[e] + part[e + 64] + part[e + 128] + part[e + 192];
        __syncthreads();
        if (tid == 0) {
            double m = -1e300;
            for (int q = 0; q < 64; q++) if (lg[q] > m) m = lg[q];
            double Z = 0.0, b1 = -1e300, b2 = -1e300;
            int i1 = 0, i2 = 0;
            for (int q = 0; q < 64; q++) {
                double x = lg[q];
                Z += exp(x - m);
                if (x > b1)      { b2 = b1; i2 = i1; b1 = x; i1 = q; }
                else if (x > b2) { b2 = x;  i2 = q; }
            }
            double s1 = exp(b1 - m) / Z;
            double s2 = exp(b2 - m) / Z;
            double den = s1 + s2 + 1e-20;

            int o1 = (int)out[gt * 2 + 0];
            int o2 = (int)out[gt * 2 + 1];
            const int b = gt >> 12;
            if (o1 != i1) { atomicAdd(&g_cnt[b * NE + o1], -1); atomicAdd(&g_cnt[b * NE + i1], 1); }
            if (o2 != i2) { atomicAdd(&g_cnt[b * NE + o2], -1); atomicAdd(&g_cnt[b * NE + i2], 1); }

            out[gt * 2 + 0] = (float)i1;
            out[gt * 2 + 1] = (float)i2;
            out[wbase + gt * 2 + 0] = (float)(s1 / den);
            out[wbase + gt * 2 + 1] = (float)(s2 / den);
        }
        __syncthreads();
    }
}

// ---------------- aux loss + scratch reset ----------------
__global__ void k_aux(float* __restrict__ out, int aux_idx) {
    __shared__ float red[NB * NE];
    int i = threadIdx.x;
    float v = (float)g_cnt[i] * ((float)NE / (float)(NS * 2)) * (g_ssum[i] / (float)NS);
    red[i] = v;
    g_cnt[i] = 0;       // reset for next graph replay
    g_ssum[i] = 0.0f;
    __syncthreads();
    for (int s = 128; s > 0; s >>= 1) {
        if (i < s) red[i] += red[i + s];
        __syncthreads();
    }
    if (i == 0) out[aux_idx] = red[0] / (float)NB * 0.1f;
}

extern "C" void kernel_launch(void* const* d_in, const int* in_sizes, int n_in,
                              void* d_out, int out_size) {
    const float* X = (const float*)d_in[0];   // [4,4096,2048] fp32
    const float* W = (const float*)d_in[1];   // [64,2048] fp32
    float* out = (float*)d_out;
    const int wbase = (out_size - 1) / 2;     // 32768

    cudaFuncSetAttribute(k_gate, cudaFuncAttributeMaxDynamicSharedMemorySize, SMEM_BYTES);

    k_wconv<<<128, 256>>>(W);
    k_gate<<<NT / TM, THREADS, SMEM_BYTES>>>(X, W, out, wbase);
    k_fixup<<<16, 256>>>(X, W, out, wbase);
    k_aux<<<1, NB * NE>>>(out, out_size - 1);
}